// round 6
// baseline (speedup 1.0000x reference)
#include <cuda_runtime.h>

#define TILE_W 64
#define TILE_H 32
#define HALO 5
#define R_ROWS (TILE_H + 2*HALO)   // 42
#define R_COLS (TILE_W + 2*HALO)   // 74
#define NTHREADS 256
#define IMG 512
#define PLANES 48
#define GRID_X (IMG / TILE_W)      // 8
#define GRID_Y (IMG / TILE_H)      // 16
#define NBLOCKS (GRID_X * GRID_Y * PLANES)  // 6144

#define C1v 0.0001f
#define C2v 0.0009f

// Union row-block layout, ROWSTRIDE=326 words (1304 B, 8B-aligned rows):
//   input (live until h write):  float2 (p,t) pairs at words [2c], c=0..74
//   h-planes (overwrite):        A=(mp,mt) pairs at [2c]      c=0..63
//                                B=(pp,tt) pairs at [128+2c]
//                                C= pt     scalar at [256+c]
// 42 * 326 = 13692 floats = 54768 B per CTA.
#define ROWSTRIDE 326
#define SMEM_BYTES (R_ROWS * ROWSTRIDE * 4)

// Gaussian(sigma=1.5, k=11); symmetric: only 6 distinct values.
__device__ constexpr float Wc[11] = {
    0.00102838f, 0.00759876f, 0.03600077f, 0.10936070f, 0.21300553f,
    0.26601172f, 0.21300553f, 0.10936070f, 0.03600077f, 0.00759876f,
    0.00102838f
};

typedef unsigned long long u64;

__device__ __forceinline__ u64 pk2(float lo, float hi) {
    u64 r; asm("mov.b64 %0, {%1, %2};" : "=l"(r) : "f"(lo), "f"(hi)); return r;
}
__device__ __forceinline__ void upk2(float& lo, float& hi, u64 v) {
    asm("mov.b64 {%0, %1}, %2;" : "=f"(lo), "=f"(hi) : "l"(v));
}
__device__ __forceinline__ u64 fma2(u64 a, u64 b, u64 c) {
    u64 d; asm("fma.rn.f32x2 %0, %1, %2, %3;" : "=l"(d) : "l"(a), "l"(b), "l"(c)); return d;
}
__device__ __forceinline__ u64 mul2(u64 a, u64 b) {
    u64 d; asm("mul.rn.f32x2 %0, %1, %2;" : "=l"(d) : "l"(a), "l"(b)); return d;
}

__device__ double g_accum = 0.0;
__device__ unsigned int g_count = 0u;

// Horizontal blur of one (row, 8-col group): packed (p,t) & (pp,tt), scalar pt.
__device__ __forceinline__ void hblur_row(const float* __restrict__ s, const u64* ww,
                                          int r, int c0,
                                          u64* am, u64* as_, float* apt) {
    #pragma unroll
    for (int o = 0; o < 8; ++o) { am[o] = 0ull; as_[o] = 0ull; apt[o] = 0.f; }
    const float* rowbase = s + r * ROWSTRIDE;
    #pragma unroll
    for (int k = 0; k < 18; ++k) {
        u64 v = *(const u64*)(rowbase + 2 * (c0 + k));   // (p,t) pair, LDS.64
        float a, b; upk2(a, b, v);
        u64 sq = mul2(v, v);                             // (pp,tt)
        float ab = a * b;
        #pragma unroll
        for (int o = 0; o < 8; ++o) {
            int tp = k - o;                              // compile-time
            if (tp >= 0 && tp < 11) {
                int wi = (tp <= 5) ? tp : 10 - tp;
                am[o]  = fma2(v,  ww[wi], am[o]);
                as_[o] = fma2(sq, ww[wi], as_[o]);
                apt[o] = fmaf(Wc[tp], ab, apt[o]);       // FFMA-imm
            }
        }
    }
}

__device__ __forceinline__ void hblur_store(float* __restrict__ s, int r, int c0,
                                            const u64* am, const u64* as_, const float* apt) {
    float* rb = s + r * ROWSTRIDE;
    #pragma unroll
    for (int o = 0; o < 8; ++o) {
        *(u64*)(rb + 2 * (c0 + o))       = am[o];        // A plane
        *(u64*)(rb + 128 + 2 * (c0 + o)) = as_[o];       // B plane
        rb[256 + c0 + o] = apt[o];                       // C plane
    }
}

__global__ __launch_bounds__(NTHREADS, 3)
void ssim_kernel(const float* __restrict__ pred, const float* __restrict__ targ,
                 float* __restrict__ out) {
    extern __shared__ float s[];
    __shared__ float red[NTHREADS / 32];

    const int tid = threadIdx.x;
    const int x0 = blockIdx.x * TILE_W;
    const int y0 = blockIdx.y * TILE_H;
    const long long plane_off = (long long)blockIdx.z * (IMG * IMG);
    const float* p = pred + plane_off;
    const float* t = targ + plane_off;

    // packed symmetric weights (6 reg pairs)
    u64 ww[6];
    #pragma unroll
    for (int i = 0; i < 6; ++i) ww[i] = pk2(Wc[i], Wc[i]);

    // ---- Phase 1: load halo tile, (x+1)/2; OOB = 0 (zero pad) ----
    {
        int r = tid / R_COLS;
        int c = tid - r * R_COLS;
        for (int idx = tid; idx < R_ROWS * R_COLS; idx += NTHREADS) {
            int gy = y0 - HALO + r;
            int gx = x0 - HALO + c;
            float a = 0.0f, b = 0.0f;
            if ((unsigned)gy < IMG && (unsigned)gx < IMG) {
                int g = gy * IMG + gx;
                a = fmaf(0.5f, p[g], 0.5f);
                b = fmaf(0.5f, t[g], 0.5f);
            }
            *(float2*)(s + r * ROWSTRIDE + 2 * c) = make_float2(a, b);
            c += NTHREADS - 3 * R_COLS;  // +34
            r += 3;
            if (c >= R_COLS) { c -= R_COLS; ++r; }
        }
    }
    __syncthreads();

    // ---- Round 1: h-blur rows 0..31 (256 units, one per thread) ----
    u64 am[8], as_[8]; float apt[8];
    const int r1 = tid & 31;             // lanes span rows (stride 326 -> conflict-free)
    const int c1 = (tid >> 5) << 3;
    hblur_row(s, ww, r1, c1, am, as_, apt);
    __syncthreads();

    // ---- Round 1 write-back + Round 2 compute rows 32..41 (80 units) ----
    hblur_store(s, r1, c1, am, as_, apt);
    const int r2 = 32 + (tid % 10);
    const int c2 = (tid / 10) << 3;
    if (tid < 80)
        hblur_row(s, ww, r2, c2, am, as_, apt);
    __syncthreads();

    if (tid < 80)
        hblur_store(s, r2, c2, am, as_, apt);
    __syncthreads();

    // ---- Phase 3: vertical blur (8-tall window) + SSIM; all 256 threads ----
    const int c  = tid & (TILE_W - 1);
    const int r0 = (tid >> 6) << 3;      // 0,8,16,24
    u64 vm[8], vs_[8]; float vpt[8];
    #pragma unroll
    for (int o = 0; o < 8; ++o) { vm[o] = 0ull; vs_[o] = 0ull; vpt[o] = 0.f; }
    #pragma unroll
    for (int k = 0; k < 18; ++k) {
        const float* rb = s + (r0 + k) * ROWSTRIDE;
        u64  hm  = *(const u64*)(rb + 2 * c);            // (mp,mt)
        u64  hs  = *(const u64*)(rb + 128 + 2 * c);      // (pp,tt)
        float hpt = rb[256 + c];
        #pragma unroll
        for (int o = 0; o < 8; ++o) {
            int tp = k - o;
            if (tp >= 0 && tp < 11) {
                int wi = (tp <= 5) ? tp : 10 - tp;
                vm[o]  = fma2(hm, ww[wi], vm[o]);
                vs_[o] = fma2(hs, ww[wi], vs_[o]);
                vpt[o] = fmaf(Wc[tp], hpt, vpt[o]);
            }
        }
    }

    float local = 0.0f;
    #pragma unroll
    for (int o = 0; o < 8; ++o) {
        float mu_p, mu_t, epp, ett;
        upk2(mu_p, mu_t, vm[o]);
        upk2(epp, ett, vs_[o]);
        float mpp = mu_p * mu_p;
        float mtt = mu_t * mu_t;
        float mpt = mu_p * mu_t;
        float sp  = epp - mpp;
        float st_ = ett - mtt;
        float spt = vpt[o] - mpt;
        float num = (2.0f * mpt + C1v) * (2.0f * spt + C2v);
        float den = (mpp + mtt + C1v) * (sp + st_ + C2v);
        local += __fdividef(num, den);
    }

    // ---- Block reduction -> device accumulator; last block finalizes ----
    #pragma unroll
    for (int sh = 16; sh > 0; sh >>= 1)
        local += __shfl_down_sync(0xffffffffu, local, sh);
    if ((tid & 31) == 0) red[tid >> 5] = local;
    __syncthreads();
    if (tid < 32) {
        float v = (tid < (NTHREADS / 32)) ? red[tid] : 0.0f;
        #pragma unroll
        for (int sh = 4; sh > 0; sh >>= 1)
            v += __shfl_down_sync(0xffffffffu, v, sh);
        if (tid == 0) {
            atomicAdd(&g_accum, (double)v);
            __threadfence();
            unsigned prev = atomicAdd(&g_count, 1u);
            if (prev == (unsigned)(NBLOCKS - 1)) {
                double tot = atomicAdd(&g_accum, 0.0);
                const double N = (double)PLANES * (double)(IMG * IMG);
                out[0] = (float)(1.0 - tot / N);
                g_accum = 0.0;
                g_count = 0u;
            }
        }
    }
}

extern "C" void kernel_launch(void* const* d_in, const int* in_sizes, int n_in,
                              void* d_out, int out_size) {
    const float* pred = (const float*)d_in[0];
    const float* targ = (const float*)d_in[1];

    cudaFuncSetAttribute(ssim_kernel, cudaFuncAttributeMaxDynamicSharedMemorySize, SMEM_BYTES);

    dim3 grid(GRID_X, GRID_Y, PLANES);
    ssim_kernel<<<grid, NTHREADS, SMEM_BYTES>>>(pred, targ, (float*)d_out);
}

// round 7
// speedup vs baseline: 1.1926x; 1.1926x over previous
#include <cuda_runtime.h>

#define TILE_W 64
#define TILE_H 32
#define HALO 5
#define R_ROWS (TILE_H + 2*HALO)   // 42
#define R_COLS (TILE_W + 2*HALO)   // 74
#define NTHREADS 256
#define IMG 512
#define PLANES 48
#define GRID_X (IMG / TILE_W)      // 8
#define GRID_Y (IMG / TILE_H)      // 16
#define NBLOCKS (GRID_X * GRID_Y * PLANES)  // 6144

#define C1v 0.0001f
#define C2v 0.0009f

// Union row-block layout, ROWSTRIDE=326 words (1304 B, 8B-aligned rows):
//   input (live until h write):  float2 (p,t) pairs at words [2c], c=0..74
//   h-planes (overwrite):        A=(mp,mt) pairs at [2c]      c=0..63
//                                B=(pp,tt) pairs at [128+2c]
//                                C= pt     scalar at [256+c]
// 42 * 326 = 13692 floats = 54768 B per CTA -> 4 CTAs/SM (219 KB of 228 KB).
#define ROWSTRIDE 326
#define SMEM_BYTES (R_ROWS * ROWSTRIDE * 4)

// Gaussian(sigma=1.5, k=11); symmetric: 6 distinct values.
__device__ constexpr float Wc[11] = {
    0.00102838f, 0.00759876f, 0.03600077f, 0.10936070f, 0.21300553f,
    0.26601172f, 0.21300553f, 0.10936070f, 0.03600077f, 0.00759876f,
    0.00102838f
};

typedef unsigned long long u64;

__device__ __forceinline__ u64 pk2(float lo, float hi) {
    u64 r; asm("mov.b64 %0, {%1, %2};" : "=l"(r) : "f"(lo), "f"(hi)); return r;
}
__device__ __forceinline__ void upk2(float& lo, float& hi, u64 v) {
    asm("mov.b64 {%0, %1}, %2;" : "=f"(lo), "=f"(hi) : "l"(v));
}
__device__ __forceinline__ u64 fma2(u64 a, u64 b, u64 c) {
    u64 d; asm("fma.rn.f32x2 %0, %1, %2, %3;" : "=l"(d) : "l"(a), "l"(b), "l"(c)); return d;
}
__device__ __forceinline__ u64 mul2(u64 a, u64 b) {
    u64 d; asm("mul.rn.f32x2 %0, %1, %2;" : "=l"(d) : "l"(a), "l"(b)); return d;
}

__device__ double g_accum = 0.0;
__device__ unsigned int g_count = 0u;

// Horizontal blur of one (row, 8-col group): packed (p,t) & (pp,tt), scalar pt.
__device__ __forceinline__ void hblur_row(const float* __restrict__ s, const u64* ww,
                                          int r, int c0,
                                          u64* am, u64* as_, float* apt) {
    #pragma unroll
    for (int o = 0; o < 8; ++o) { am[o] = 0ull; as_[o] = 0ull; apt[o] = 0.f; }
    const float* rowbase = s + r * ROWSTRIDE;
    #pragma unroll
    for (int k = 0; k < 18; ++k) {
        u64 v = *(const u64*)(rowbase + 2 * (c0 + k));   // (p,t) pair, LDS.64
        u64 sq = mul2(v, v);                             // (pp,tt)
        float a, b; upk2(a, b, v);
        float ab = a * b;
        #pragma unroll
        for (int o = 0; o < 8; ++o) {
            int tp = k - o;                              // compile-time
            if (tp >= 0 && tp < 11) {
                int wi = (tp <= 5) ? tp : 10 - tp;
                am[o]  = fma2(v,  ww[wi], am[o]);
                as_[o] = fma2(sq, ww[wi], as_[o]);
                apt[o] = fmaf(Wc[tp], ab, apt[o]);       // FFMA-imm
            }
        }
    }
}

__device__ __forceinline__ void hblur_store(float* __restrict__ s, int r, int c0,
                                            const u64* am, const u64* as_, const float* apt) {
    float* rb = s + r * ROWSTRIDE;
    #pragma unroll
    for (int o = 0; o < 8; ++o) {
        *(u64*)(rb + 2 * (c0 + o))       = am[o];        // A plane
        *(u64*)(rb + 128 + 2 * (c0 + o)) = as_[o];       // B plane
        rb[256 + c0 + o] = apt[o];                       // C plane
    }
}

__global__ __launch_bounds__(NTHREADS, 4)   // cap regs at 64 -> 4 CTAs/SM
void ssim_kernel(const float* __restrict__ pred, const float* __restrict__ targ,
                 float* __restrict__ out) {
    extern __shared__ float s[];
    __shared__ float red[NTHREADS / 32];

    const int tid = threadIdx.x;
    const int x0 = blockIdx.x * TILE_W;
    const int y0 = blockIdx.y * TILE_H;
    const long long plane_off = (long long)blockIdx.z * (IMG * IMG);
    const float* p = pred + plane_off;
    const float* t = targ + plane_off;

    // packed symmetric weights (6 reg pairs; thread-invariant)
    u64 ww[6];
    #pragma unroll
    for (int i = 0; i < 6; ++i) ww[i] = pk2(Wc[i], Wc[i]);

    // ---- Phase 1: load halo tile, (x+1)/2; OOB = 0 (zero pad) ----
    {
        int r = tid / R_COLS;
        int c = tid - r * R_COLS;
        for (int idx = tid; idx < R_ROWS * R_COLS; idx += NTHREADS) {
            int gy = y0 - HALO + r;
            int gx = x0 - HALO + c;
            float a = 0.0f, b = 0.0f;
            if ((unsigned)gy < IMG && (unsigned)gx < IMG) {
                int g = gy * IMG + gx;
                a = fmaf(0.5f, p[g], 0.5f);
                b = fmaf(0.5f, t[g], 0.5f);
            }
            *(float2*)(s + r * ROWSTRIDE + 2 * c) = make_float2(a, b);
            c += NTHREADS - 3 * R_COLS;  // +34
            r += 3;
            if (c >= R_COLS) { c -= R_COLS; ++r; }
        }
    }
    __syncthreads();

    // ---- Round 1: h-blur rows 0..31 (256 units, one per thread) ----
    u64 am[8], as_[8]; float apt[8];
    const int r1 = tid & 31;             // lanes span rows (stride 326 -> conflict-free)
    const int c1 = (tid >> 5) << 3;
    hblur_row(s, ww, r1, c1, am, as_, apt);
    __syncthreads();

    // ---- Round 1 write-back + Round 2 compute rows 32..41 (80 units) ----
    hblur_store(s, r1, c1, am, as_, apt);
    const int r2 = 32 + (tid % 10);
    const int c2 = (tid / 10) << 3;
    if (tid < 80)
        hblur_row(s, ww, r2, c2, am, as_, apt);
    __syncthreads();

    if (tid < 80)
        hblur_store(s, r2, c2, am, as_, apt);
    __syncthreads();

    // ---- Phase 3: vertical blur (8-tall window) + SSIM; all 256 threads ----
    const int c  = tid & (TILE_W - 1);
    const int r0 = (tid >> 6) << 3;      // 0,8,16,24
    u64 vm[8], vs_[8]; float vpt[8];
    #pragma unroll
    for (int o = 0; o < 8; ++o) { vm[o] = 0ull; vs_[o] = 0ull; vpt[o] = 0.f; }
    #pragma unroll
    for (int k = 0; k < 18; ++k) {
        const float* rb = s + (r0 + k) * ROWSTRIDE;
        u64  hm  = *(const u64*)(rb + 2 * c);            // (mp,mt)
        u64  hs  = *(const u64*)(rb + 128 + 2 * c);      // (pp,tt)
        float hpt = rb[256 + c];
        #pragma unroll
        for (int o = 0; o < 8; ++o) {
            int tp = k - o;
            if (tp >= 0 && tp < 11) {
                int wi = (tp <= 5) ? tp : 10 - tp;
                vm[o]  = fma2(hm, ww[wi], vm[o]);
                vs_[o] = fma2(hs, ww[wi], vs_[o]);
                vpt[o] = fmaf(Wc[tp], hpt, vpt[o]);
            }
        }
    }

    float local = 0.0f;
    #pragma unroll
    for (int o = 0; o < 8; ++o) {
        float mu_p, mu_t, epp, ett;
        upk2(mu_p, mu_t, vm[o]);
        upk2(epp, ett, vs_[o]);
        float mpp = mu_p * mu_p;
        float mtt = mu_t * mu_t;
        float mpt = mu_p * mu_t;
        float sp  = epp - mpp;
        float st_ = ett - mtt;
        float spt = vpt[o] - mpt;
        float num = (2.0f * mpt + C1v) * (2.0f * spt + C2v);
        float den = (mpp + mtt + C1v) * (sp + st_ + C2v);
        local += __fdividef(num, den);
    }

    // ---- Block reduction -> device accumulator; last block finalizes ----
    #pragma unroll
    for (int sh = 16; sh > 0; sh >>= 1)
        local += __shfl_down_sync(0xffffffffu, local, sh);
    if ((tid & 31) == 0) red[tid >> 5] = local;
    __syncthreads();
    if (tid < 32) {
        float v = (tid < (NTHREADS / 32)) ? red[tid] : 0.0f;
        #pragma unroll
        for (int sh = 4; sh > 0; sh >>= 1)
            v += __shfl_down_sync(0xffffffffu, v, sh);
        if (tid == 0) {
            atomicAdd(&g_accum, (double)v);
            __threadfence();
            unsigned prev = atomicAdd(&g_count, 1u);
            if (prev == (unsigned)(NBLOCKS - 1)) {
                double tot = atomicAdd(&g_accum, 0.0);
                const double N = (double)PLANES * (double)(IMG * IMG);
                out[0] = (float)(1.0 - tot / N);
                g_accum = 0.0;
                g_count = 0u;
            }
        }
    }
}

extern "C" void kernel_launch(void* const* d_in, const int* in_sizes, int n_in,
                              void* d_out, int out_size) {
    const float* pred = (const float*)d_in[0];
    const float* targ = (const float*)d_in[1];

    cudaFuncSetAttribute(ssim_kernel, cudaFuncAttributeMaxDynamicSharedMemorySize, SMEM_BYTES);

    dim3 grid(GRID_X, GRID_Y, PLANES);
    ssim_kernel<<<grid, NTHREADS, SMEM_BYTES>>>(pred, targ, (float*)d_out);
}

// round 8
// speedup vs baseline: 1.5551x; 1.3039x over previous
#include <cuda_runtime.h>

#define TILE_W 64
#define TILE_H 32
#define HALO 5
#define R_ROWS (TILE_H + 2*HALO)   // 42
#define R_COLS (TILE_W + 2*HALO)   // 74
#define NTHREADS 256
#define IMG 512
#define PLANES 48
#define GRID_X (IMG / TILE_W)      // 8
#define GRID_Y (IMG / TILE_H)      // 16
#define NBLOCKS (GRID_X * GRID_Y * PLANES)  // 6144

#define C1v 0.0001f
#define C2v 0.0009f

// Union row-block layout, ROWSTRIDE=326 words (1304 B, 8B-aligned rows):
//   input (live until h write):  float2 (p,t) pairs at words [2c], c=0..74
//   h-planes (overwrite):        A=(mp,mt) pairs at [2c]      c=0..63
//                                B=(pp,tt) pairs at [128+2c]
//                                C= pt     scalar at [256+c]
// 42 * 326 = 13692 floats = 54768 B per CTA -> 4 CTAs/SM.
#define ROWSTRIDE 326
#define SMEM_BYTES (R_ROWS * ROWSTRIDE * 4)

// Gaussian(sigma=1.5, k=11); symmetric: 6 distinct values.
__device__ constexpr float Wc[11] = {
    0.00102838f, 0.00759876f, 0.03600077f, 0.10936070f, 0.21300553f,
    0.26601172f, 0.21300553f, 0.10936070f, 0.03600077f, 0.00759876f,
    0.00102838f
};

typedef unsigned long long u64;

__device__ __forceinline__ u64 pk2(float lo, float hi) {
    u64 r; asm("mov.b64 %0, {%1, %2};" : "=l"(r) : "f"(lo), "f"(hi)); return r;
}
__device__ __forceinline__ void upk2(float& lo, float& hi, u64 v) {
    asm("mov.b64 {%0, %1}, %2;" : "=f"(lo), "=f"(hi) : "l"(v));
}
__device__ __forceinline__ u64 fma2(u64 a, u64 b, u64 c) {
    u64 d; asm("fma.rn.f32x2 %0, %1, %2, %3;" : "=l"(d) : "l"(a), "l"(b), "l"(c)); return d;
}
__device__ __forceinline__ u64 mul2(u64 a, u64 b) {
    u64 d; asm("mul.rn.f32x2 %0, %1, %2;" : "=l"(d) : "l"(a), "l"(b)); return d;
}

__device__ double g_accum = 0.0;
__device__ unsigned int g_count = 0u;

// Horizontal blur: W-wide column group at (r, c0). Packed (p,t),(pp,tt), scalar pt.
template<int W>
__device__ __forceinline__ void hblur_row(const float* __restrict__ s, const u64* ww,
                                          int r, int c0,
                                          u64* am, u64* as_, float* apt) {
    #pragma unroll
    for (int o = 0; o < W; ++o) { am[o] = 0ull; as_[o] = 0ull; apt[o] = 0.f; }
    const float* rowbase = s + r * ROWSTRIDE;
    #pragma unroll
    for (int k = 0; k < W + 10; ++k) {
        u64 v = *(const u64*)(rowbase + 2 * (c0 + k));   // (p,t) pair, LDS.64
        u64 sq = mul2(v, v);                             // (pp,tt)
        float a, b; upk2(a, b, v);
        float ab = a * b;
        #pragma unroll
        for (int o = 0; o < W; ++o) {
            int tp = k - o;                              // compile-time
            if (tp >= 0 && tp < 11) {
                int wi = (tp <= 5) ? tp : 10 - tp;
                am[o]  = fma2(v,  ww[wi], am[o]);
                as_[o] = fma2(sq, ww[wi], as_[o]);
                apt[o] = fmaf(Wc[tp], ab, apt[o]);       // FFMA-imm
            }
        }
    }
}

template<int W>
__device__ __forceinline__ void hblur_store(float* __restrict__ s, int r, int c0,
                                            const u64* am, const u64* as_, const float* apt) {
    float* rb = s + r * ROWSTRIDE;
    #pragma unroll
    for (int o = 0; o < W; ++o) {
        *(u64*)(rb + 2 * (c0 + o))       = am[o];        // A plane
        *(u64*)(rb + 128 + 2 * (c0 + o)) = as_[o];       // B plane
        rb[256 + c0 + o] = apt[o];                       // C plane
    }
}

__global__ __launch_bounds__(NTHREADS, 4)   // cap regs at 64 -> 4 CTAs/SM
void ssim_kernel(const float* __restrict__ pred, const float* __restrict__ targ,
                 float* __restrict__ out) {
    extern __shared__ float s[];
    __shared__ float red[NTHREADS / 32];

    const int tid = threadIdx.x;
    const int x0 = blockIdx.x * TILE_W;
    const int y0 = blockIdx.y * TILE_H;
    const long long plane_off = (long long)blockIdx.z * (IMG * IMG);
    const float* p = pred + plane_off;
    const float* t = targ + plane_off;

    // packed symmetric weights (6 reg pairs; thread-invariant)
    u64 ww[6];
    #pragma unroll
    for (int i = 0; i < 6; ++i) ww[i] = pk2(Wc[i], Wc[i]);

    // ---- Phase 1: load halo tile, (x+1)/2; OOB = 0 (zero pad) ----
    // Unrolled, predicated iterations: front-batched LDGs -> high MLP.
    #pragma unroll
    for (int i = 0; i < 13; ++i) {
        int idx = tid + i * NTHREADS;
        if (idx < R_ROWS * R_COLS) {
            int r = idx / R_COLS;
            int c = idx - r * R_COLS;
            int gy = y0 - HALO + r;
            int gx = x0 - HALO + c;
            float a = 0.0f, b = 0.0f;
            if ((unsigned)gy < IMG && (unsigned)gx < IMG) {
                int g = gy * IMG + gx;
                a = fmaf(0.5f, p[g], 0.5f);
                b = fmaf(0.5f, t[g], 0.5f);
            }
            *(float2*)(s + r * ROWSTRIDE + 2 * c) = make_float2(a, b);
        }
    }
    __syncthreads();

    // ---- Round 1: h-blur rows 0..31, 8-wide (256 units, one per thread) ----
    u64 am[8], as_[8]; float apt[8];
    const int r1 = tid & 31;             // lanes span rows (stride 326 -> conflict-free)
    const int c1 = (tid >> 5) << 3;
    hblur_row<8>(s, ww, r1, c1, am, as_, apt);
    __syncthreads();

    // ---- Round 1 write-back + Round 2 compute rows 32..41, 4-wide ----
    // 10 rows x 16 groups = 160 units, one per thread -> half-length critical path.
    hblur_store<8>(s, r1, c1, am, as_, apt);
    const int r2 = 32 + (tid % 10);
    const int c2 = (tid / 10) << 2;
    if (tid < 160)
        hblur_row<4>(s, ww, r2, c2, am, as_, apt);
    __syncthreads();

    if (tid < 160)
        hblur_store<4>(s, r2, c2, am, as_, apt);
    __syncthreads();

    // ---- Phase 3: vertical blur (8-tall window) + SSIM; all 256 threads ----
    const int c  = tid & (TILE_W - 1);
    const int r0 = (tid >> 6) << 3;      // 0,8,16,24
    u64 vm[8], vs_[8]; float vpt[8];
    #pragma unroll
    for (int o = 0; o < 8; ++o) { vm[o] = 0ull; vs_[o] = 0ull; vpt[o] = 0.f; }
    #pragma unroll
    for (int k = 0; k < 18; ++k) {
        const float* rb = s + (r0 + k) * ROWSTRIDE;
        u64  hm  = *(const u64*)(rb + 2 * c);            // (mp,mt)
        u64  hs  = *(const u64*)(rb + 128 + 2 * c);      // (pp,tt)
        float hpt = rb[256 + c];
        #pragma unroll
        for (int o = 0; o < 8; ++o) {
            int tp = k - o;
            if (tp >= 0 && tp < 11) {
                int wi = (tp <= 5) ? tp : 10 - tp;
                vm[o]  = fma2(hm, ww[wi], vm[o]);
                vs_[o] = fma2(hs, ww[wi], vs_[o]);
                vpt[o] = fmaf(Wc[tp], hpt, vpt[o]);
            }
        }
    }

    float local = 0.0f;
    #pragma unroll
    for (int o = 0; o < 8; ++o) {
        float mu_p, mu_t, epp, ett;
        upk2(mu_p, mu_t, vm[o]);
        upk2(epp, ett, vs_[o]);
        float mpp = mu_p * mu_p;
        float mtt = mu_t * mu_t;
        float mpt = mu_p * mu_t;
        float sp  = epp - mpp;
        float st_ = ett - mtt;
        float spt = vpt[o] - mpt;
        float num = (2.0f * mpt + C1v) * (2.0f * spt + C2v);
        float den = (mpp + mtt + C1v) * (sp + st_ + C2v);
        local += __fdividef(num, den);
    }

    // ---- Block reduction -> device accumulator; last block finalizes ----
    #pragma unroll
    for (int sh = 16; sh > 0; sh >>= 1)
        local += __shfl_down_sync(0xffffffffu, local, sh);
    if ((tid & 31) == 0) red[tid >> 5] = local;
    __syncthreads();
    if (tid < 32) {
        float v = (tid < (NTHREADS / 32)) ? red[tid] : 0.0f;
        #pragma unroll
        for (int sh = 4; sh > 0; sh >>= 1)
            v += __shfl_down_sync(0xffffffffu, v, sh);
        if (tid == 0) {
            atomicAdd(&g_accum, (double)v);
            __threadfence();
            unsigned prev = atomicAdd(&g_count, 1u);
            if (prev == (unsigned)(NBLOCKS - 1)) {
                double tot = atomicAdd(&g_accum, 0.0);
                const double N = (double)PLANES * (double)(IMG * IMG);
                out[0] = (float)(1.0 - tot / N);
                g_accum = 0.0;
                g_count = 0u;
            }
        }
    }
}

extern "C" void kernel_launch(void* const* d_in, const int* in_sizes, int n_in,
                              void* d_out, int out_size) {
    const float* pred = (const float*)d_in[0];
    const float* targ = (const float*)d_in[1];

    cudaFuncSetAttribute(ssim_kernel, cudaFuncAttributeMaxDynamicSharedMemorySize, SMEM_BYTES);

    dim3 grid(GRID_X, GRID_Y, PLANES);
    ssim_kernel<<<grid, NTHREADS, SMEM_BYTES>>>(pred, targ, (float*)d_out);
}